// round 4
// baseline (speedup 1.0000x reference)
#include <cuda_runtime.h>

// ---------------------------------------------------------------------------
// MultiAgentCommSystem — fully fused, one CTA per batch (4096 CTAs x 256 thr)
//
// Pipeline per batch b (N=64 agents), entirely in 128KB shared memory:
//   1. load obs[b]            (64x128)                       -> s_obs
//   2. h   = relu(obs@W1+b1)  (64x128, K=128)                -> s_big
//   3. msg = h@W2+b2          (64x64,  K=128)                -> s_c  (+gmem)
//   4. qkv = msg@Wqkv+b       (64x192, K=64)                 -> s_big
//   5. attention (H=4, HD=16), softmax over 64 keys          -> s_c
//   6. agg = ctx@Wo+bo        (64x64,  K=64)                 -> s_d
//   7. z   = [obs,agg]@Wi1+b  (64x256, K=192)                -> s_big
//   8. LayerNorm(256) + ReLU in place
//   9. out = z@Wi2+b          (64x128, K=256)                -> gmem
//
// All GEMM inner loops use packed fp32x2 FMA (fma.rn.f32x2) — exact fp32
// arithmetic at 2x issue density on sm_103a.
// ---------------------------------------------------------------------------

typedef unsigned long long ull;
#define DEV __device__ __forceinline__

DEV ull pack2(float x) {
    ull r; asm("mov.b64 %0, {%1, %1};" : "=l"(r) : "f"(x)); return r;
}
DEV void fma2(ull& acc, ull a, ull w) {
    asm("fma.rn.f32x2 %0, %1, %2, %0;" : "+l"(acc) : "l"(a), "l"(w));
}
DEV float2 unpack2(ull v) {
    float2 f; asm("mov.b64 {%0, %1}, %2;" : "=f"(f.x), "=f"(f.y) : "l"(v)); return f;
}

// C[64][NC] = act(A[64][K] @ W[K][NC] + bias); A in smem, W in gmem (L2-hot).
// Thread map: 16 row-groups x 16 col-groups; 4 rows x (NC/16) cols per thread.
template<int K, int NC, int LDA, int LDC, bool RELU>
DEV void gemm_smem(const float* __restrict__ sA, const float* __restrict__ W,
                   const float* __restrict__ bias, float* __restrict__ sC, int tid)
{
    constexpr int CPT = NC / 16;   // cols per thread (always even)
    constexpr int NP  = CPT / 2;   // packed f32x2 pairs
    const int r0 = (tid >> 4) << 2;
    const int c0 = (tid & 15) * CPT;

    ull acc[4][NP];
    #pragma unroll
    for (int i = 0; i < 4; i++)
        #pragma unroll
        for (int j = 0; j < NP; j++) acc[i][j] = 0ull;

    const float* Wc = W + c0;
    #pragma unroll 4
    for (int k = 0; k < K; k++) {
        const ull* wr = (const ull*)(Wc + k * NC);
        ull w2[NP];
        #pragma unroll
        for (int j = 0; j < NP; j++) w2[j] = wr[j];
        #pragma unroll
        for (int i = 0; i < 4; i++) {
            ull a2 = pack2(sA[(r0 + i) * LDA + k]);   // 16-lane smem broadcast
            #pragma unroll
            for (int j = 0; j < NP; j++) fma2(acc[i][j], a2, w2[j]);
        }
    }
    #pragma unroll
    for (int i = 0; i < 4; i++) {
        #pragma unroll
        for (int j = 0; j < NP; j++) {
            float2 v = unpack2(acc[i][j]);
            v.x += bias[c0 + 2 * j];
            v.y += bias[c0 + 2 * j + 1];
            if (RELU) { v.x = fmaxf(v.x, 0.f); v.y = fmaxf(v.y, 0.f); }
            *(float2*)(sC + (r0 + i) * LDC + c0 + 2 * j) = v;
        }
    }
}

// z[64][256] = [obs(128) | agg(64)] @ Wi1[192][256] + b  (concat GEMM, K split)
DEV void gemm_integrate(const float* __restrict__ sObs, const float* __restrict__ sAgg,
                        const float* __restrict__ W, const float* __restrict__ bias,
                        float* __restrict__ sZ, int tid)
{
    constexpr int NC = 256, CPT = 16, NP = 8;
    const int r0 = (tid >> 4) << 2;
    const int c0 = (tid & 15) * CPT;

    ull acc[4][NP];
    #pragma unroll
    for (int i = 0; i < 4; i++)
        #pragma unroll
        for (int j = 0; j < NP; j++) acc[i][j] = 0ull;

    const float* Wc = W + c0;
    #pragma unroll 4
    for (int k = 0; k < 128; k++) {
        const ull* wr = (const ull*)(Wc + k * NC);
        ull w2[NP];
        #pragma unroll
        for (int j = 0; j < NP; j++) w2[j] = wr[j];
        #pragma unroll
        for (int i = 0; i < 4; i++) {
            ull a2 = pack2(sObs[(r0 + i) * 128 + k]);
            #pragma unroll
            for (int j = 0; j < NP; j++) fma2(acc[i][j], a2, w2[j]);
        }
    }
    #pragma unroll 4
    for (int k = 0; k < 64; k++) {
        const ull* wr = (const ull*)(Wc + (128 + k) * NC);
        ull w2[NP];
        #pragma unroll
        for (int j = 0; j < NP; j++) w2[j] = wr[j];
        #pragma unroll
        for (int i = 0; i < 4; i++) {
            ull a2 = pack2(sAgg[(r0 + i) * 64 + k]);
            #pragma unroll
            for (int j = 0; j < NP; j++) fma2(acc[i][j], a2, w2[j]);
        }
    }
    #pragma unroll
    for (int i = 0; i < 4; i++) {
        #pragma unroll
        for (int j = 0; j < NP; j++) {
            float2 v = unpack2(acc[i][j]);
            v.x += bias[c0 + 2 * j];
            v.y += bias[c0 + 2 * j + 1];
            *(float2*)(sZ + (r0 + i) * 256 + c0 + 2 * j) = v;
        }
    }
}

// out[64][128] = relu'd-z[64][256] @ Wi2[256][128] + b  -> gmem (enriched)
DEV void gemm_final(const float* __restrict__ sZ, const float* __restrict__ W,
                    const float* __restrict__ bias, float* __restrict__ gOut, int tid)
{
    constexpr int NC = 128, CPT = 8, NP = 4;
    const int r0 = (tid >> 4) << 2;
    const int c0 = (tid & 15) * CPT;

    ull acc[4][NP];
    #pragma unroll
    for (int i = 0; i < 4; i++)
        #pragma unroll
        for (int j = 0; j < NP; j++) acc[i][j] = 0ull;

    const float* Wc = W + c0;
    #pragma unroll 4
    for (int k = 0; k < 256; k++) {
        const ull* wr = (const ull*)(Wc + k * NC);
        ull w2[NP];
        #pragma unroll
        for (int j = 0; j < NP; j++) w2[j] = wr[j];
        #pragma unroll
        for (int i = 0; i < 4; i++) {
            ull a2 = pack2(sZ[(r0 + i) * 256 + k]);
            #pragma unroll
            for (int j = 0; j < NP; j++) fma2(acc[i][j], a2, w2[j]);
        }
    }
    #pragma unroll
    for (int i = 0; i < 4; i++) {
        #pragma unroll
        for (int j = 0; j < NP; j++) {
            float2 v = unpack2(acc[i][j]);
            v.x += bias[c0 + 2 * j];
            v.y += bias[c0 + 2 * j + 1];
            *(float2*)(gOut + (r0 + i) * 128 + c0 + 2 * j) = v;
        }
    }
}

// 4 heads, HD=16, 64 keys. One warp = one (head, 32-q-row block). Scores kept
// fully in registers; softmax scale folded into q.
DEV void attention(const float* __restrict__ sQKV /*64x192*/,
                   float* __restrict__ sCtx /*64x64*/, int tid)
{
    const int warp = tid >> 5;
    const int lane = tid & 31;
    const int head = warp >> 1;
    const int qrow = ((warp & 1) << 5) + lane;

    const float* qp = sQKV + qrow * 192 + head * 16;
    float q[16];
    #pragma unroll
    for (int d = 0; d < 16; d++) q[d] = qp[d] * 0.25f;   // 1/sqrt(16)

    float s[64];
    #pragma unroll
    for (int j = 0; j < 64; j++) {
        const float4* kp = (const float4*)(sQKV + j * 192 + 64 + head * 16);
        float a = 0.f;
        #pragma unroll
        for (int t = 0; t < 4; t++) {
            float4 kv = kp[t];  // broadcast: all lanes same address
            a += q[4*t+0]*kv.x + q[4*t+1]*kv.y + q[4*t+2]*kv.z + q[4*t+3]*kv.w;
        }
        s[j] = a;
    }
    float m = s[0];
    #pragma unroll
    for (int j = 1; j < 64; j++) m = fmaxf(m, s[j]);
    float sum = 0.f;
    #pragma unroll
    for (int j = 0; j < 64; j++) { s[j] = __expf(s[j] - m); sum += s[j]; }
    const float inv = 1.f / sum;

    float acc[16];
    #pragma unroll
    for (int d = 0; d < 16; d++) acc[d] = 0.f;
    #pragma unroll
    for (int j = 0; j < 64; j++) {
        const float4* vp = (const float4*)(sQKV + j * 192 + 128 + head * 16);
        float p = s[j];
        #pragma unroll
        for (int t = 0; t < 4; t++) {
            float4 vv = vp[t];
            acc[4*t+0] += p * vv.x; acc[4*t+1] += p * vv.y;
            acc[4*t+2] += p * vv.z; acc[4*t+3] += p * vv.w;
        }
    }
    float* cp = sCtx + qrow * 64 + head * 16;
    #pragma unroll
    for (int d = 0; d < 16; d++) cp[d] = acc[d] * inv;
}

DEV void layernorm_relu(float* __restrict__ sZ /*64x256*/,
                        const float* __restrict__ g, const float* __restrict__ b, int tid)
{
    const int warp = tid >> 5, lane = tid & 31;
    for (int row = warp; row < 64; row += 8) {
        float* zp = sZ + row * 256;
        float v[8], sum = 0.f, sq = 0.f;
        #pragma unroll
        for (int t = 0; t < 8; t++) {
            v[t] = zp[lane + 32 * t];
            sum += v[t]; sq += v[t] * v[t];
        }
        #pragma unroll
        for (int o = 16; o > 0; o >>= 1) {
            sum += __shfl_xor_sync(0xffffffffu, sum, o);
            sq  += __shfl_xor_sync(0xffffffffu, sq, o);
        }
        const float mu  = sum * (1.f / 256.f);
        const float var = sq * (1.f / 256.f) - mu * mu;
        const float rs  = rsqrtf(var + 1e-5f);
        #pragma unroll
        for (int t = 0; t < 8; t++) {
            const int c = lane + 32 * t;
            float y = (v[t] - mu) * rs * g[c] + b[c];
            zp[c] = fmaxf(y, 0.f);
        }
    }
}

__global__ void __launch_bounds__(256, 1)
comm_kernel(const float* __restrict__ obs,
            const float* __restrict__ enc_w1, const float* __restrict__ enc_b1,
            const float* __restrict__ enc_w2, const float* __restrict__ enc_b2,
            const float* __restrict__ in_proj_w, const float* __restrict__ in_proj_b,
            const float* __restrict__ out_w, const float* __restrict__ out_b,
            const float* __restrict__ int_w1, const float* __restrict__ int_b1,
            const float* __restrict__ ln_g, const float* __restrict__ ln_b,
            const float* __restrict__ int_w2, const float* __restrict__ int_b2,
            float* __restrict__ out_enriched, float* __restrict__ out_msgs)
{
    extern __shared__ float smem[];
    float* s_obs = smem;              // 64*128 = 8192 floats
    float* s_big = smem + 8192;       // 64*256 = 16384 floats (h / qkv / z)
    float* s_c   = smem + 24576;      // 64*64  = 4096 floats  (msgs / ctx)
    float* s_d   = smem + 28672;      // 64*64  = 4096 floats  (agg)

    const int b   = blockIdx.x;
    const int tid = threadIdx.x;

    // load obs tile: 8192 floats = 2048 float4, 8 per thread
    {
        const float4* g = (const float4*)(obs + (size_t)b * 8192);
        float4* sd = (float4*)s_obs;
        #pragma unroll
        for (int i = 0; i < 8; i++) sd[tid + i * 256] = g[tid + i * 256];
    }
    __syncthreads();

    // 1) h = relu(obs @ enc_w1 + b1)
    gemm_smem<128, 128, 128, 128, true>(s_obs, enc_w1, enc_b1, s_big, tid);
    __syncthreads();

    // 2) msgs = h @ enc_w2 + b2
    gemm_smem<128, 64, 128, 64, false>(s_big, enc_w2, enc_b2, s_c, tid);
    __syncthreads();

    // write msgs output (second tuple element)
    {
        float4* g = (float4*)(out_msgs + (size_t)b * 4096);
        const float4* sd = (const float4*)s_c;
        #pragma unroll
        for (int i = 0; i < 4; i++) g[tid + i * 256] = sd[tid + i * 256];
    }

    // 3) qkv = msgs @ in_proj_w + b
    gemm_smem<64, 192, 64, 192, false>(s_c, in_proj_w, in_proj_b, s_big, tid);
    __syncthreads();

    // 4) attention -> ctx (overwrites msgs, no longer needed)
    attention(s_big, s_c, tid);
    __syncthreads();

    // 5) agg = ctx @ out_w + b
    gemm_smem<64, 64, 64, 64, false>(s_c, out_w, out_b, s_d, tid);
    __syncthreads();

    // 6) z = [obs | agg] @ int_w1 + b (overwrites qkv)
    gemm_integrate(s_obs, s_d, int_w1, int_b1, s_big, tid);
    __syncthreads();

    // 7) LayerNorm + ReLU in place
    layernorm_relu(s_big, ln_g, ln_b, tid);
    __syncthreads();

    // 8) enriched = z @ int_w2 + b -> gmem
    gemm_final(s_big, int_w2, int_b2, out_enriched + (size_t)b * 8192, tid);
}

extern "C" void kernel_launch(void* const* d_in, const int* in_sizes, int n_in,
                              void* d_out, int out_size)
{
    const float* obs       = (const float*)d_in[0];
    const float* enc_w1    = (const float*)d_in[1];
    const float* enc_b1    = (const float*)d_in[2];
    const float* enc_w2    = (const float*)d_in[3];
    const float* enc_b2    = (const float*)d_in[4];
    const float* in_proj_w = (const float*)d_in[5];
    const float* in_proj_b = (const float*)d_in[6];
    const float* out_w     = (const float*)d_in[7];
    const float* out_b     = (const float*)d_in[8];
    const float* int_w1    = (const float*)d_in[9];
    const float* int_b1    = (const float*)d_in[10];
    const float* ln_g      = (const float*)d_in[11];
    const float* ln_b      = (const float*)d_in[12];
    const float* int_w2    = (const float*)d_in[13];
    const float* int_b2    = (const float*)d_in[14];

    float* out_enriched = (float*)d_out;                       // (B,N,128)
    float* out_msgs     = (float*)d_out + (size_t)4096 * 64 * 128;  // (B,N,64)

    const int smem_bytes = 32768 * sizeof(float);  // 131072
    cudaFuncSetAttribute(comm_kernel, cudaFuncAttributeMaxDynamicSharedMemorySize, smem_bytes);

    comm_kernel<<<4096, 256, smem_bytes>>>(
        obs, enc_w1, enc_b1, enc_w2, enc_b2,
        in_proj_w, in_proj_b, out_w, out_b,
        int_w1, int_b1, ln_g, ln_b, int_w2, int_b2,
        out_enriched, out_msgs);
}

// round 5
// speedup vs baseline: 2.4771x; 2.4771x over previous
#include <cuda_runtime.h>

// ---------------------------------------------------------------------------
// MultiAgentCommSystem — fully fused, one CTA per batch (4096 CTAs x 256 thr)
//
// R4 change vs R2: L1tex wavefront-bound fix.
//  * W columns interleaved per thread: pair j -> cols {2*(tid&15)+32j}.
//    Each LDG.64 now touches exactly ONE 128B line (1 wavefront) instead of
//    4-8 lines with the old blocked map.
//  * A operand read as LDS.128 per 4-k block (1 wavefront per row-quad)
//    instead of 4 scalar broadcast LDS.
// FFMA2 (fma.rn.f32x2) kept: exact fp32, 2x density.
// ---------------------------------------------------------------------------

typedef unsigned long long ull;
#define DEV __device__ __forceinline__

DEV ull pack2(float x) {
    ull r; asm("mov.b64 %0, {%1, %1};" : "=l"(r) : "f"(x)); return r;
}
DEV void fma2(ull& acc, ull a, ull w) {
    asm("fma.rn.f32x2 %0, %1, %2, %0;" : "+l"(acc) : "l"(a), "l"(w));
}
DEV float2 unpack2(ull v) {
    float2 f; asm("mov.b64 {%0, %1}, %2;" : "=f"(f.x), "=f"(f.y) : "l"(v)); return f;
}
DEV float elem4(const float4& v, int kk) {
    return kk == 0 ? v.x : kk == 1 ? v.y : kk == 2 ? v.z : v.w;
}

// Accumulate: acc[4][NP] += A[64xK](rows r0..r0+3) @ W[KxNC](cols c0+32j,+1)
// A in smem (row-major, leading dim LDA), W in gmem (L2/L1-hot).
template<int K, int NC, int LDA>
DEV void gemm_acc(const float* __restrict__ sA, const float* __restrict__ W,
                  ull* __restrict__ acc, int r0, int c0)
{
    constexpr int NP = NC / 32;
    #pragma unroll 2
    for (int k4 = 0; k4 < K; k4 += 4) {
        // 4 rows x 4 k-values: one LDS.128 per row (1 wavefront per warp)
        float4 a0 = *(const float4*)(sA + (r0 + 0) * LDA + k4);
        float4 a1 = *(const float4*)(sA + (r0 + 1) * LDA + k4);
        float4 a2 = *(const float4*)(sA + (r0 + 2) * LDA + k4);
        float4 a3 = *(const float4*)(sA + (r0 + 3) * LDA + k4);
        #pragma unroll
        for (int kk = 0; kk < 4; kk++) {
            // 16 lanes read one contiguous 128B line per j: 1 wavefront
            const ull* wr = (const ull*)(W + (k4 + kk) * NC + c0);
            ull w2[NP];
            #pragma unroll
            for (int j = 0; j < NP; j++) w2[j] = wr[16 * j];
            ull b0 = pack2(elem4(a0, kk));
            ull b1 = pack2(elem4(a1, kk));
            ull b2 = pack2(elem4(a2, kk));
            ull b3 = pack2(elem4(a3, kk));
            #pragma unroll
            for (int j = 0; j < NP; j++) {
                fma2(acc[0 * NP + j], b0, w2[j]);
                fma2(acc[1 * NP + j], b1, w2[j]);
                fma2(acc[2 * NP + j], b2, w2[j]);
                fma2(acc[3 * NP + j], b3, w2[j]);
            }
        }
    }
}

template<int NC, int LDC, bool RELU>
DEV void gemm_store(const ull* __restrict__ acc, const float* __restrict__ bias,
                    float* __restrict__ C, int r0, int c0)
{
    constexpr int NP = NC / 32;
    #pragma unroll
    for (int i = 0; i < 4; i++) {
        #pragma unroll
        for (int j = 0; j < NP; j++) {
            const int col = c0 + 32 * j;
            float2 v = unpack2(acc[i * NP + j]);
            v.x += bias[col];
            v.y += bias[col + 1];
            if (RELU) { v.x = fmaxf(v.x, 0.f); v.y = fmaxf(v.y, 0.f); }
            *(float2*)(C + (r0 + i) * LDC + col) = v;   // 128B contiguous per (i,j)
        }
    }
}

template<int K, int NC, int LDA, int LDC, bool RELU>
DEV void gemm(const float* __restrict__ sA, const float* __restrict__ W,
              const float* __restrict__ bias, float* __restrict__ C, int tid)
{
    constexpr int NP = NC / 32;
    const int r0 = (tid >> 4) << 2;
    const int c0 = (tid & 15) * 2;
    ull acc[4 * NP];
    #pragma unroll
    for (int i = 0; i < 4 * NP; i++) acc[i] = 0ull;
    gemm_acc<K, NC, LDA>(sA, W, acc, r0, c0);
    gemm_store<NC, LDC, RELU>(acc, bias, C, r0, c0);
}

// z[64][256] = [obs(128) | agg(64)] @ Wi1[192][256] + b
DEV void gemm_integrate(const float* __restrict__ sObs, const float* __restrict__ sAgg,
                        const float* __restrict__ W, const float* __restrict__ bias,
                        float* __restrict__ sZ, int tid)
{
    constexpr int NP = 8;  // NC=256
    const int r0 = (tid >> 4) << 2;
    const int c0 = (tid & 15) * 2;
    ull acc[4 * NP];
    #pragma unroll
    for (int i = 0; i < 4 * NP; i++) acc[i] = 0ull;
    gemm_acc<128, 256, 128>(sObs, W, acc, r0, c0);
    gemm_acc<64, 256, 64>(sAgg, W + 128 * 256, acc, r0, c0);
    gemm_store<256, 256, false>(acc, bias, sZ, r0, c0);
}

// 4 heads, HD=16, 64 keys. One warp = one (head, 32-q-row block).
DEV void attention(const float* __restrict__ sQKV /*64x192*/,
                   float* __restrict__ sCtx /*64x64*/, int tid)
{
    const int warp = tid >> 5;
    const int lane = tid & 31;
    const int head = warp >> 1;
    const int qrow = ((warp & 1) << 5) + lane;

    const float* qp = sQKV + qrow * 192 + head * 16;
    float q[16];
    #pragma unroll
    for (int d = 0; d < 16; d++) q[d] = qp[d] * 0.25f;   // 1/sqrt(16)

    float s[64];
    #pragma unroll
    for (int j = 0; j < 64; j++) {
        const float4* kp = (const float4*)(sQKV + j * 192 + 64 + head * 16);
        float a = 0.f;
        #pragma unroll
        for (int t = 0; t < 4; t++) {
            float4 kv = kp[t];
            a += q[4*t+0]*kv.x + q[4*t+1]*kv.y + q[4*t+2]*kv.z + q[4*t+3]*kv.w;
        }
        s[j] = a;
    }
    float m = s[0];
    #pragma unroll
    for (int j = 1; j < 64; j++) m = fmaxf(m, s[j]);
    float sum = 0.f;
    #pragma unroll
    for (int j = 0; j < 64; j++) { s[j] = __expf(s[j] - m); sum += s[j]; }
    const float inv = 1.f / sum;

    float acc[16];
    #pragma unroll
    for (int d = 0; d < 16; d++) acc[d] = 0.f;
    #pragma unroll
    for (int j = 0; j < 64; j++) {
        const float4* vp = (const float4*)(sQKV + j * 192 + 128 + head * 16);
        float p = s[j];
        #pragma unroll
        for (int t = 0; t < 4; t++) {
            float4 vv = vp[t];
            acc[4*t+0] += p * vv.x; acc[4*t+1] += p * vv.y;
            acc[4*t+2] += p * vv.z; acc[4*t+3] += p * vv.w;
        }
    }
    float* cp = sCtx + qrow * 64 + head * 16;
    #pragma unroll
    for (int d = 0; d < 16; d++) cp[d] = acc[d] * inv;
}

DEV void layernorm_relu(float* __restrict__ sZ /*64x256*/,
                        const float* __restrict__ g, const float* __restrict__ b, int tid)
{
    const int warp = tid >> 5, lane = tid & 31;
    for (int row = warp; row < 64; row += 8) {
        float* zp = sZ + row * 256;
        float v[8], sum = 0.f, sq = 0.f;
        #pragma unroll
        for (int t = 0; t < 8; t++) {
            v[t] = zp[lane + 32 * t];
            sum += v[t]; sq += v[t] * v[t];
        }
        #pragma unroll
        for (int o = 16; o > 0; o >>= 1) {
            sum += __shfl_xor_sync(0xffffffffu, sum, o);
            sq  += __shfl_xor_sync(0xffffffffu, sq, o);
        }
        const float mu  = sum * (1.f / 256.f);
        const float var = sq * (1.f / 256.f) - mu * mu;
        const float rs  = rsqrtf(var + 1e-5f);
        #pragma unroll
        for (int t = 0; t < 8; t++) {
            const int c = lane + 32 * t;
            float y = (v[t] - mu) * rs * g[c] + b[c];
            zp[c] = fmaxf(y, 0.f);
        }
    }
}

__global__ void __launch_bounds__(256, 1)
comm_kernel(const float* __restrict__ obs,
            const float* __restrict__ enc_w1, const float* __restrict__ enc_b1,
            const float* __restrict__ enc_w2, const float* __restrict__ enc_b2,
            const float* __restrict__ in_proj_w, const float* __restrict__ in_proj_b,
            const float* __restrict__ out_w, const float* __restrict__ out_b,
            const float* __restrict__ int_w1, const float* __restrict__ int_b1,
            const float* __restrict__ ln_g, const float* __restrict__ ln_b,
            const float* __restrict__ int_w2, const float* __restrict__ int_b2,
            float* __restrict__ out_enriched, float* __restrict__ out_msgs)
{
    extern __shared__ float smem[];
    float* s_obs = smem;              // 64*128 = 8192 floats
    float* s_big = smem + 8192;       // 64*256 = 16384 floats (h / qkv / z)
    float* s_c   = smem + 24576;      // 64*64  = 4096 floats  (msgs / ctx)
    float* s_d   = smem + 28672;      // 64*64  = 4096 floats  (agg)

    const int b   = blockIdx.x;
    const int tid = threadIdx.x;

    // load obs tile: 8192 floats = 2048 float4, 8 per thread
    {
        const float4* g = (const float4*)(obs + (size_t)b * 8192);
        float4* sd = (float4*)s_obs;
        #pragma unroll
        for (int i = 0; i < 8; i++) sd[tid + i * 256] = g[tid + i * 256];
    }
    __syncthreads();

    // 1) h = relu(obs @ enc_w1 + b1)
    gemm<128, 128, 128, 128, true>(s_obs, enc_w1, enc_b1, s_big, tid);
    __syncthreads();

    // 2) msgs = h @ enc_w2 + b2
    gemm<128, 64, 128, 64, false>(s_big, enc_w2, enc_b2, s_c, tid);
    __syncthreads();

    // write msgs output (second tuple element)
    {
        float4* g = (float4*)(out_msgs + (size_t)b * 4096);
        const float4* sd = (const float4*)s_c;
        #pragma unroll
        for (int i = 0; i < 4; i++) g[tid + i * 256] = sd[tid + i * 256];
    }

    // 3) qkv = msgs @ in_proj_w + b
    gemm<64, 192, 64, 192, false>(s_c, in_proj_w, in_proj_b, s_big, tid);
    __syncthreads();

    // 4) attention -> ctx (overwrites msgs)
    attention(s_big, s_c, tid);
    __syncthreads();

    // 5) agg = ctx @ out_w + b
    gemm<64, 64, 64, 64, false>(s_c, out_w, out_b, s_d, tid);
    __syncthreads();

    // 6) z = [obs | agg] @ int_w1 + b (overwrites qkv)
    gemm_integrate(s_obs, s_d, int_w1, int_b1, s_big, tid);
    __syncthreads();

    // 7) LayerNorm + ReLU in place
    layernorm_relu(s_big, ln_g, ln_b, tid);
    __syncthreads();

    // 8) enriched = z @ int_w2 + b -> gmem
    gemm<256, 128, 256, 128, false>(s_big, int_w2, int_b2,
                                    out_enriched + (size_t)b * 8192, tid);
}

extern "C" void kernel_launch(void* const* d_in, const int* in_sizes, int n_in,
                              void* d_out, int out_size)
{
    const float* obs       = (const float*)d_in[0];
    const float* enc_w1    = (const float*)d_in[1];
    const float* enc_b1    = (const float*)d_in[2];
    const float* enc_w2    = (const float*)d_in[3];
    const float* enc_b2    = (const float*)d_in[4];
    const float* in_proj_w = (const float*)d_in[5];
    const float* in_proj_b = (const float*)d_in[6];
    const float* out_w     = (const float*)d_in[7];
    const float* out_b     = (const float*)d_in[8];
    const float* int_w1    = (const float*)d_in[9];
    const float* int_b1    = (const float*)d_in[10];
    const float* ln_g      = (const float*)d_in[11];
    const float* ln_b      = (const float*)d_in[12];
    const float* int_w2    = (const float*)d_in[13];
    const float* int_b2    = (const float*)d_in[14];

    float* out_enriched = (float*)d_out;                            // (B,N,128)
    float* out_msgs     = (float*)d_out + (size_t)4096 * 64 * 128;  // (B,N,64)

    const int smem_bytes = 32768 * sizeof(float);  // 131072
    cudaFuncSetAttribute(comm_kernel, cudaFuncAttributeMaxDynamicSharedMemorySize, smem_bytes);

    comm_kernel<<<4096, 256, smem_bytes>>>(
        obs, enc_w1, enc_b1, enc_w2, enc_b2,
        in_proj_w, in_proj_b, out_w, out_b,
        int_w1, int_b1, ln_g, ln_b, int_w2, int_b2,
        out_enriched, out_msgs);
}

// round 7
// speedup vs baseline: 3.2415x; 1.3086x over previous
#include <cuda_runtime.h>

// ---------------------------------------------------------------------------
// MultiAgentCommSystem — fused, one CTA per batch, R6: 2 CTAs/SM.
//  (R5 resubmit with the dead template wrapper removed — compile fix.)
//
//  * smem 128KB -> 112KB (agg reuses the ctx buffer after a sync) so two
//    CTAs co-reside per SM (4 warps/SMSP instead of 2).
//  * __launch_bounds__(256, 2): regs capped at 128. The NC=256 integrate
//    GEMM is split into two 128-column passes (acc 32 regs, was 64).
//  * W loaded as LDG.128 (float4 per thread, 16 lanes = 256B): half the
//    load instructions, 2x MLP per instruction, same wavefronts/byte.
// FFMA2 (fma.rn.f32x2) kept everywhere: exact fp32 at 2x issue density.
// ---------------------------------------------------------------------------

typedef unsigned long long ull;
#define DEV __device__ __forceinline__

DEV ull pack2(float x) {
    ull r; asm("mov.b64 %0, {%1, %1};" : "=l"(r) : "f"(x)); return r;
}
DEV void fma2(ull& acc, ull a, ull w) {
    asm("fma.rn.f32x2 %0, %1, %2, %0;" : "+l"(acc) : "l"(a), "l"(w));
}
DEV float2 unpack2(ull v) {
    float2 f; asm("mov.b64 {%0, %1}, %2;" : "=f"(f.x), "=f"(f.y) : "l"(v)); return f;
}
DEV float elem4(const float4& v, int kk) {
    return kk == 0 ? v.x : kk == 1 ? v.y : kk == 2 ? v.z : v.w;
}

// acc[4][G][2] += A[64xK](rows r0..r0+3) @ W[KxLDW](cols c0+64g .. +3)
// A in smem (LDS.128 per 4-k block, 2-addr broadcast), W in gmem (LDG.128,
// 16 lanes x 16B = 256B contiguous).
template<int K, int G, int LDA, int LDW>
DEV void gemm_acc(const float* __restrict__ sA, const float* __restrict__ W,
                  ull (&acc)[4][G][2], int r0, int c0)
{
    #pragma unroll 2
    for (int k4 = 0; k4 < K; k4 += 4) {
        float4 a0 = *(const float4*)(sA + (r0 + 0) * LDA + k4);
        float4 a1 = *(const float4*)(sA + (r0 + 1) * LDA + k4);
        float4 a2 = *(const float4*)(sA + (r0 + 2) * LDA + k4);
        float4 a3 = *(const float4*)(sA + (r0 + 3) * LDA + k4);
        #pragma unroll
        for (int kk = 0; kk < 4; kk++) {
            ulonglong2 w[G];
            #pragma unroll
            for (int g = 0; g < G; g++)
                w[g] = *(const ulonglong2*)(W + (k4 + kk) * LDW + c0 + 64 * g);
            ull b0 = pack2(elem4(a0, kk));
            ull b1 = pack2(elem4(a1, kk));
            ull b2 = pack2(elem4(a2, kk));
            ull b3 = pack2(elem4(a3, kk));
            #pragma unroll
            for (int g = 0; g < G; g++) {
                fma2(acc[0][g][0], b0, w[g].x); fma2(acc[0][g][1], b0, w[g].y);
                fma2(acc[1][g][0], b1, w[g].x); fma2(acc[1][g][1], b1, w[g].y);
                fma2(acc[2][g][0], b2, w[g].x); fma2(acc[2][g][1], b2, w[g].y);
                fma2(acc[3][g][0], b3, w[g].x); fma2(acc[3][g][1], b3, w[g].y);
            }
        }
    }
}

template<int G, int LDC, bool RELU>
DEV void gemm_store(const ull (&acc)[4][G][2], const float* __restrict__ bias,
                    float* __restrict__ C, int r0, int c0)
{
    #pragma unroll
    for (int g = 0; g < G; g++) {
        const int col = c0 + 64 * g;
        float4 bv = *(const float4*)(bias + col);
        #pragma unroll
        for (int i = 0; i < 4; i++) {
            float2 lo = unpack2(acc[i][g][0]);
            float2 hi = unpack2(acc[i][g][1]);
            float4 v = make_float4(lo.x + bv.x, lo.y + bv.y, hi.x + bv.z, hi.y + bv.w);
            if (RELU) {
                v.x = fmaxf(v.x, 0.f); v.y = fmaxf(v.y, 0.f);
                v.z = fmaxf(v.z, 0.f); v.w = fmaxf(v.w, 0.f);
            }
            *(float4*)(C + (r0 + i) * LDC + col) = v;
        }
    }
}

// 4 heads, HD=16, 64 keys. One warp = one (head, 32-q-row block).
DEV void attention(const float* __restrict__ sQKV /*64x192*/,
                   float* __restrict__ sCtx /*64x64*/, int tid)
{
    const int warp = tid >> 5;
    const int lane = tid & 31;
    const int head = warp >> 1;
    const int qrow = ((warp & 1) << 5) + lane;

    const float* qp = sQKV + qrow * 192 + head * 16;
    float q[16];
    #pragma unroll
    for (int d = 0; d < 16; d++) q[d] = qp[d] * 0.25f;   // 1/sqrt(16)

    float s[64];
    #pragma unroll
    for (int j = 0; j < 64; j++) {
        const float4* kp = (const float4*)(sQKV + j * 192 + 64 + head * 16);
        float a = 0.f;
        #pragma unroll
        for (int t = 0; t < 4; t++) {
            float4 kv = kp[t];
            a += q[4*t+0]*kv.x + q[4*t+1]*kv.y + q[4*t+2]*kv.z + q[4*t+3]*kv.w;
        }
        s[j] = a;
    }
    float m = s[0];
    #pragma unroll
    for (int j = 1; j < 64; j++) m = fmaxf(m, s[j]);
    float sum = 0.f;
    #pragma unroll
    for (int j = 0; j < 64; j++) { s[j] = __expf(s[j] - m); sum += s[j]; }
    const float inv = 1.f / sum;

    float acc[16];
    #pragma unroll
    for (int d = 0; d < 16; d++) acc[d] = 0.f;
    #pragma unroll
    for (int j = 0; j < 64; j++) {
        const float4* vp = (const float4*)(sQKV + j * 192 + 128 + head * 16);
        float p = s[j];
        #pragma unroll
        for (int t = 0; t < 4; t++) {
            float4 vv = vp[t];
            acc[4*t+0] += p * vv.x; acc[4*t+1] += p * vv.y;
            acc[4*t+2] += p * vv.z; acc[4*t+3] += p * vv.w;
        }
    }
    float* cp = sCtx + qrow * 64 + head * 16;
    #pragma unroll
    for (int d = 0; d < 16; d++) cp[d] = acc[d] * inv;
}

DEV void layernorm_relu(float* __restrict__ sZ /*64x256*/,
                        const float* __restrict__ g, const float* __restrict__ b, int tid)
{
    const int warp = tid >> 5, lane = tid & 31;
    for (int row = warp; row < 64; row += 8) {
        float* zp = sZ + row * 256;
        float v[8], sum = 0.f, sq = 0.f;
        #pragma unroll
        for (int t = 0; t < 8; t++) {
            v[t] = zp[lane + 32 * t];
            sum += v[t]; sq += v[t] * v[t];
        }
        #pragma unroll
        for (int o = 16; o > 0; o >>= 1) {
            sum += __shfl_xor_sync(0xffffffffu, sum, o);
            sq  += __shfl_xor_sync(0xffffffffu, sq, o);
        }
        const float mu  = sum * (1.f / 256.f);
        const float var = sq * (1.f / 256.f) - mu * mu;
        const float rs  = rsqrtf(var + 1e-5f);
        #pragma unroll
        for (int t = 0; t < 8; t++) {
            const int c = lane + 32 * t;
            float y = (v[t] - mu) * rs * g[c] + b[c];
            zp[c] = fmaxf(y, 0.f);
        }
    }
}

__global__ void __launch_bounds__(256, 2)
comm_kernel(const float* __restrict__ obs,
            const float* __restrict__ enc_w1, const float* __restrict__ enc_b1,
            const float* __restrict__ enc_w2, const float* __restrict__ enc_b2,
            const float* __restrict__ in_proj_w, const float* __restrict__ in_proj_b,
            const float* __restrict__ out_w, const float* __restrict__ out_b,
            const float* __restrict__ int_w1, const float* __restrict__ int_b1,
            const float* __restrict__ ln_g, const float* __restrict__ ln_b,
            const float* __restrict__ int_w2, const float* __restrict__ int_b2,
            float* __restrict__ out_enriched, float* __restrict__ out_msgs)
{
    extern __shared__ float smem[];
    float* s_obs = smem;              // 64*128 = 8192 floats (32KB)
    float* s_big = smem + 8192;       // 64*256 = 16384 floats (64KB): h/qkv/z
    float* s_c   = smem + 24576;      // 64*64  = 4096 floats (16KB): msgs/ctx/agg
    // total 28672 floats = 112KB -> 2 CTAs/SM

    const int b   = blockIdx.x;
    const int tid = threadIdx.x;
    const int r0  = (tid >> 4) << 2;
    const int c0  = (tid & 15) * 4;

    // load obs tile: 8192 floats = 2048 float4, 8 per thread
    {
        const float4* g = (const float4*)(obs + (size_t)b * 8192);
        float4* sd = (float4*)s_obs;
        #pragma unroll
        for (int i = 0; i < 8; i++) sd[tid + i * 256] = g[tid + i * 256];
    }
    __syncthreads();

    // 1) h = relu(obs @ enc_w1 + b1)   (K=128, NC=128)
    {
        ull acc[4][2][2];
        #pragma unroll
        for (int i = 0; i < 4; i++)
            #pragma unroll
            for (int g = 0; g < 2; g++) { acc[i][g][0] = 0; acc[i][g][1] = 0; }
        gemm_acc<128, 2, 128, 128>(s_obs, enc_w1, acc, r0, c0);
        gemm_store<2, 128, true>(acc, enc_b1, s_big, r0, c0);
    }
    __syncthreads();

    // 2) msgs = h @ enc_w2 + b2   (K=128, NC=64)
    {
        ull acc[4][1][2];
        #pragma unroll
        for (int i = 0; i < 4; i++) { acc[i][0][0] = 0; acc[i][0][1] = 0; }
        gemm_acc<128, 1, 128, 64>(s_big, enc_w2, acc, r0, c0);
        gemm_store<1, 64, false>(acc, enc_b2, s_c, r0, c0);
    }
    __syncthreads();

    // write msgs output (second tuple element)
    {
        float4* g = (float4*)(out_msgs + (size_t)b * 4096);
        const float4* sd = (const float4*)s_c;
        #pragma unroll
        for (int i = 0; i < 4; i++) g[tid + i * 256] = sd[tid + i * 256];
    }

    // 3) qkv = msgs @ in_proj_w + b   (K=64, NC=192)
    {
        ull acc[4][3][2];
        #pragma unroll
        for (int i = 0; i < 4; i++)
            #pragma unroll
            for (int g = 0; g < 3; g++) { acc[i][g][0] = 0; acc[i][g][1] = 0; }
        gemm_acc<64, 3, 64, 192>(s_c, in_proj_w, acc, r0, c0);
        gemm_store<3, 192, false>(acc, in_proj_b, s_big, r0, c0);
    }
    __syncthreads();

    // 4) attention -> ctx (overwrites msgs; msgs already flushed)
    attention(s_big, s_c, tid);
    __syncthreads();

    // 5) agg = ctx @ out_w + b  (K=64, NC=64); agg overwrites ctx after sync
    {
        ull acc[4][1][2];
        #pragma unroll
        for (int i = 0; i < 4; i++) { acc[i][0][0] = 0; acc[i][0][1] = 0; }
        gemm_acc<64, 1, 64, 64>(s_c, out_w, acc, r0, c0);
        __syncthreads();                       // all ctx reads done
        gemm_store<1, 64, false>(acc, out_b, s_c, r0, c0);   // s_c now = agg
    }
    __syncthreads();

    // 6) z = [obs | agg] @ int_w1 + b  (K=192, NC=256), two 128-col passes
    #pragma unroll
    for (int p = 0; p < 2; p++) {
        ull acc[4][2][2];
        #pragma unroll
        for (int i = 0; i < 4; i++)
            #pragma unroll
            for (int g = 0; g < 2; g++) { acc[i][g][0] = 0; acc[i][g][1] = 0; }
        const float* Wp = int_w1 + p * 128;
        gemm_acc<128, 2, 128, 256>(s_obs, Wp, acc, r0, c0);
        gemm_acc<64, 2, 64, 256>(s_c, Wp + 128 * 256, acc, r0, c0);
        gemm_store<2, 256, false>(acc, int_b1 + p * 128, s_big + p * 128, r0, c0);
    }
    __syncthreads();

    // 7) LayerNorm + ReLU in place
    layernorm_relu(s_big, ln_g, ln_b, tid);
    __syncthreads();

    // 8) enriched = z @ int_w2 + b -> gmem   (K=256, NC=128)
    {
        ull acc[4][2][2];
        #pragma unroll
        for (int i = 0; i < 4; i++)
            #pragma unroll
            for (int g = 0; g < 2; g++) { acc[i][g][0] = 0; acc[i][g][1] = 0; }
        gemm_acc<256, 2, 256, 128>(s_big, int_w2, acc, r0, c0);
        gemm_store<2, 128, false>(acc, int_b2, out_enriched + (size_t)b * 8192, r0, c0);
    }
}

extern "C" void kernel_launch(void* const* d_in, const int* in_sizes, int n_in,
                              void* d_out, int out_size)
{
    const float* obs       = (const float*)d_in[0];
    const float* enc_w1    = (const float*)d_in[1];
    const float* enc_b1    = (const float*)d_in[2];
    const float* enc_w2    = (const float*)d_in[3];
    const float* enc_b2    = (const float*)d_in[4];
    const float* in_proj_w = (const float*)d_in[5];
    const float* in_proj_b = (const float*)d_in[6];
    const float* out_w     = (const float*)d_in[7];
    const float* out_b     = (const float*)d_in[8];
    const float* int_w1    = (const float*)d_in[9];
    const float* int_b1    = (const float*)d_in[10];
    const float* ln_g      = (const float*)d_in[11];
    const float* ln_b      = (const float*)d_in[12];
    const float* int_w2    = (const float*)d_in[13];
    const float* int_b2    = (const float*)d_in[14];

    float* out_enriched = (float*)d_out;                            // (B,N,128)
    float* out_msgs     = (float*)d_out + (size_t)4096 * 64 * 128;  // (B,N,64)

    const int smem_bytes = 28672 * sizeof(float);  // 114688 = 112KB
    cudaFuncSetAttribute(comm_kernel, cudaFuncAttributeMaxDynamicSharedMemorySize, smem_bytes);

    comm_kernel<<<4096, 256, smem_bytes>>>(
        obs, enc_w1, enc_b1, enc_w2, enc_b2,
        in_proj_w, in_proj_b, out_w, out_b,
        int_w1, int_b1, ln_g, ln_b, int_w2, int_b2,
        out_enriched, out_msgs);
}

// round 8
// speedup vs baseline: 3.2462x; 1.0015x over previous
#include <cuda_runtime.h>

// ---------------------------------------------------------------------------
// MultiAgentCommSystem — fused, one CTA per batch, R6: 2 CTAs/SM.
//  (R5 resubmit with the dead template wrapper removed — compile fix.)
//
//  * smem 128KB -> 112KB (agg reuses the ctx buffer after a sync) so two
//    CTAs co-reside per SM (4 warps/SMSP instead of 2).
//  * __launch_bounds__(256, 2): regs capped at 128. The NC=256 integrate
//    GEMM is split into two 128-column passes (acc 32 regs, was 64).
//  * W loaded as LDG.128 (float4 per thread, 16 lanes = 256B): half the
//    load instructions, 2x MLP per instruction, same wavefronts/byte.
// FFMA2 (fma.rn.f32x2) kept everywhere: exact fp32 at 2x issue density.
// ---------------------------------------------------------------------------

typedef unsigned long long ull;
#define DEV __device__ __forceinline__

DEV ull pack2(float x) {
    ull r; asm("mov.b64 %0, {%1, %1};" : "=l"(r) : "f"(x)); return r;
}
DEV void fma2(ull& acc, ull a, ull w) {
    asm("fma.rn.f32x2 %0, %1, %2, %0;" : "+l"(acc) : "l"(a), "l"(w));
}
DEV float2 unpack2(ull v) {
    float2 f; asm("mov.b64 {%0, %1}, %2;" : "=f"(f.x), "=f"(f.y) : "l"(v)); return f;
}
DEV float elem4(const float4& v, int kk) {
    return kk == 0 ? v.x : kk == 1 ? v.y : kk == 2 ? v.z : v.w;
}

// acc[4][G][2] += A[64xK](rows r0..r0+3) @ W[KxLDW](cols c0+64g .. +3)
// A in smem (LDS.128 per 4-k block, 2-addr broadcast), W in gmem (LDG.128,
// 16 lanes x 16B = 256B contiguous).
template<int K, int G, int LDA, int LDW>
DEV void gemm_acc(const float* __restrict__ sA, const float* __restrict__ W,
                  ull (&acc)[4][G][2], int r0, int c0)
{
    #pragma unroll 2
    for (int k4 = 0; k4 < K; k4 += 4) {
        float4 a0 = *(const float4*)(sA + (r0 + 0) * LDA + k4);
        float4 a1 = *(const float4*)(sA + (r0 + 1) * LDA + k4);
        float4 a2 = *(const float4*)(sA + (r0 + 2) * LDA + k4);
        float4 a3 = *(const float4*)(sA + (r0 + 3) * LDA + k4);
        #pragma unroll
        for (int kk = 0; kk < 4; kk++) {
            ulonglong2 w[G];
            #pragma unroll
            for (int g = 0; g < G; g++)
                w[g] = *(const ulonglong2*)(W + (k4 + kk) * LDW + c0 + 64 * g);
            ull b0 = pack2(elem4(a0, kk));
            ull b1 = pack2(elem4(a1, kk));
            ull b2 = pack2(elem4(a2, kk));
            ull b3 = pack2(elem4(a3, kk));
            #pragma unroll
            for (int g = 0; g < G; g++) {
                fma2(acc[0][g][0], b0, w[g].x); fma2(acc[0][g][1], b0, w[g].y);
                fma2(acc[1][g][0], b1, w[g].x); fma2(acc[1][g][1], b1, w[g].y);
                fma2(acc[2][g][0], b2, w[g].x); fma2(acc[2][g][1], b2, w[g].y);
                fma2(acc[3][g][0], b3, w[g].x); fma2(acc[3][g][1], b3, w[g].y);
            }
        }
    }
}

template<int G, int LDC, bool RELU>
DEV void gemm_store(const ull (&acc)[4][G][2], const float* __restrict__ bias,
                    float* __restrict__ C, int r0, int c0)
{
    #pragma unroll
    for (int g = 0; g < G; g++) {
        const int col = c0 + 64 * g;
        float4 bv = *(const float4*)(bias + col);
        #pragma unroll
        for (int i = 0; i < 4; i++) {
            float2 lo = unpack2(acc[i][g][0]);
            float2 hi = unpack2(acc[i][g][1]);
            float4 v = make_float4(lo.x + bv.x, lo.y + bv.y, hi.x + bv.z, hi.y + bv.w);
            if (RELU) {
                v.x = fmaxf(v.x, 0.f); v.y = fmaxf(v.y, 0.f);
                v.z = fmaxf(v.z, 0.f); v.w = fmaxf(v.w, 0.f);
            }
            *(float4*)(C + (r0 + i) * LDC + col) = v;
        }
    }
}

// 4 heads, HD=16, 64 keys. One warp = one (head, 32-q-row block).
DEV void attention(const float* __restrict__ sQKV /*64x192*/,
                   float* __restrict__ sCtx /*64x64*/, int tid)
{
    const int warp = tid >> 5;
    const int lane = tid & 31;
    const int head = warp >> 1;
    const int qrow = ((warp & 1) << 5) + lane;

    const float* qp = sQKV + qrow * 192 + head * 16;
    float q[16];
    #pragma unroll
    for (int d = 0; d < 16; d++) q[d] = qp[d] * 0.25f;   // 1/sqrt(16)

    float s[64];
    #pragma unroll
    for (int j = 0; j < 64; j++) {
        const float4* kp = (const float4*)(sQKV + j * 192 + 64 + head * 16);
        float a = 0.f;
        #pragma unroll
        for (int t = 0; t < 4; t++) {
            float4 kv = kp[t];
            a += q[4*t+0]*kv.x + q[4*t+1]*kv.y + q[4*t+2]*kv.z + q[4*t+3]*kv.w;
        }
        s[j] = a;
    }
    float m = s[0];
    #pragma unroll
    for (int j = 1; j < 64; j++) m = fmaxf(m, s[j]);
    float sum = 0.f;
    #pragma unroll
    for (int j = 0; j < 64; j++) { s[j] = __expf(s[j] - m); sum += s[j]; }
    const float inv = 1.f / sum;

    float acc[16];
    #pragma unroll
    for (int d = 0; d < 16; d++) acc[d] = 0.f;
    #pragma unroll
    for (int j = 0; j < 64; j++) {
        const float4* vp = (const float4*)(sQKV + j * 192 + 128 + head * 16);
        float p = s[j];
        #pragma unroll
        for (int t = 0; t < 4; t++) {
            float4 vv = vp[t];
            acc[4*t+0] += p * vv.x; acc[4*t+1] += p * vv.y;
            acc[4*t+2] += p * vv.z; acc[4*t+3] += p * vv.w;
        }
    }
    float* cp = sCtx + qrow * 64 + head * 16;
    #pragma unroll
    for (int d = 0; d < 16; d++) cp[d] = acc[d] * inv;
}

DEV void layernorm_relu(float* __restrict__ sZ /*64x256*/,
                        const float* __restrict__ g, const float* __restrict__ b, int tid)
{
    const int warp = tid >> 5, lane = tid & 31;
    for (int row = warp; row < 64; row += 8) {
        float* zp = sZ + row * 256;
        float v[8], sum = 0.f, sq = 0.f;
        #pragma unroll
        for (int t = 0; t < 8; t++) {
            v[t] = zp[lane + 32 * t];
            sum += v[t]; sq += v[t] * v[t];
        }
        #pragma unroll
        for (int o = 16; o > 0; o >>= 1) {
            sum += __shfl_xor_sync(0xffffffffu, sum, o);
            sq  += __shfl_xor_sync(0xffffffffu, sq, o);
        }
        const float mu  = sum * (1.f / 256.f);
        const float var = sq * (1.f / 256.f) - mu * mu;
        const float rs  = rsqrtf(var + 1e-5f);
        #pragma unroll
        for (int t = 0; t < 8; t++) {
            const int c = lane + 32 * t;
            float y = (v[t] - mu) * rs * g[c] + b[c];
            zp[c] = fmaxf(y, 0.f);
        }
    }
}

__global__ void __launch_bounds__(256, 2)
comm_kernel(const float* __restrict__ obs,
            const float* __restrict__ enc_w1, const float* __restrict__ enc_b1,
            const float* __restrict__ enc_w2, const float* __restrict__ enc_b2,
            const float* __restrict__ in_proj_w, const float* __restrict__ in_proj_b,
            const float* __restrict__ out_w, const float* __restrict__ out_b,
            const float* __restrict__ int_w1, const float* __restrict__ int_b1,
            const float* __restrict__ ln_g, const float* __restrict__ ln_b,
            const float* __restrict__ int_w2, const float* __restrict__ int_b2,
            float* __restrict__ out_enriched, float* __restrict__ out_msgs)
{
    extern __shared__ float smem[];
    float* s_obs = smem;              // 64*128 = 8192 floats (32KB)
    float* s_big = smem + 8192;       // 64*256 = 16384 floats (64KB): h/qkv/z
    float* s_c   = smem + 24576;      // 64*64  = 4096 floats (16KB): msgs/ctx/agg
    // total 28672 floats = 112KB -> 2 CTAs/SM

    const int b   = blockIdx.x;
    const int tid = threadIdx.x;
    const int r0  = (tid >> 4) << 2;
    const int c0  = (tid & 15) * 4;

    // load obs tile: 8192 floats = 2048 float4, 8 per thread
    {
        const float4* g = (const float4*)(obs + (size_t)b * 8192);
        float4* sd = (float4*)s_obs;
        #pragma unroll
        for (int i = 0; i < 8; i++) sd[tid + i * 256] = g[tid + i * 256];
    }
    __syncthreads();

    // 1) h = relu(obs @ enc_w1 + b1)   (K=128, NC=128)
    {
        ull acc[4][2][2];
        #pragma unroll
        for (int i = 0; i < 4; i++)
            #pragma unroll
            for (int g = 0; g < 2; g++) { acc[i][g][0] = 0; acc[i][g][1] = 0; }
        gemm_acc<128, 2, 128, 128>(s_obs, enc_w1, acc, r0, c0);
        gemm_store<2, 128, true>(acc, enc_b1, s_big, r0, c0);
    }
    __syncthreads();

    // 2) msgs = h @ enc_w2 + b2   (K=128, NC=64)
    {
        ull acc[4][1][2];
        #pragma unroll
        for (int i = 0; i < 4; i++) { acc[i][0][0] = 0; acc[i][0][1] = 0; }
        gemm_acc<128, 1, 128, 64>(s_big, enc_w2, acc, r0, c0);
        gemm_store<1, 64, false>(acc, enc_b2, s_c, r0, c0);
    }
    __syncthreads();

    // write msgs output (second tuple element)
    {
        float4* g = (float4*)(out_msgs + (size_t)b * 4096);
        const float4* sd = (const float4*)s_c;
        #pragma unroll
        for (int i = 0; i < 4; i++) g[tid + i * 256] = sd[tid + i * 256];
    }

    // 3) qkv = msgs @ in_proj_w + b   (K=64, NC=192)
    {
        ull acc[4][3][2];
        #pragma unroll
        for (int i = 0; i < 4; i++)
            #pragma unroll
            for (int g = 0; g < 3; g++) { acc[i][g][0] = 0; acc[i][g][1] = 0; }
        gemm_acc<64, 3, 64, 192>(s_c, in_proj_w, acc, r0, c0);
        gemm_store<3, 192, false>(acc, in_proj_b, s_big, r0, c0);
    }
    __syncthreads();

    // 4) attention -> ctx (overwrites msgs; msgs already flushed)
    attention(s_big, s_c, tid);
    __syncthreads();

    // 5) agg = ctx @ out_w + b  (K=64, NC=64); agg overwrites ctx after sync
    {
        ull acc[4][1][2];
        #pragma unroll
        for (int i = 0; i < 4; i++) { acc[i][0][0] = 0; acc[i][0][1] = 0; }
        gemm_acc<64, 1, 64, 64>(s_c, out_w, acc, r0, c0);
        __syncthreads();                       // all ctx reads done
        gemm_store<1, 64, false>(acc, out_b, s_c, r0, c0);   // s_c now = agg
    }
    __syncthreads();

    // 6) z = [obs | agg] @ int_w1 + b  (K=192, NC=256), two 128-col passes
    #pragma unroll
    for (int p = 0; p < 2; p++) {
        ull acc[4][2][2];
        #pragma unroll
        for (int i = 0; i < 4; i++)
            #pragma unroll
            for (int g = 0; g < 2; g++) { acc[i][g][0] = 0; acc[i][g][1] = 0; }
        const float* Wp = int_w1 + p * 128;
        gemm_acc<128, 2, 128, 256>(s_obs, Wp, acc, r0, c0);
        gemm_acc<64, 2, 64, 256>(s_c, Wp + 128 * 256, acc, r0, c0);
        gemm_store<2, 256, false>(acc, int_b1 + p * 128, s_big + p * 128, r0, c0);
    }
    __syncthreads();

    // 7) LayerNorm + ReLU in place
    layernorm_relu(s_big, ln_g, ln_b, tid);
    __syncthreads();

    // 8) enriched = z @ int_w2 + b -> gmem   (K=256, NC=128)
    {
        ull acc[4][2][2];
        #pragma unroll
        for (int i = 0; i < 4; i++)
            #pragma unroll
            for (int g = 0; g < 2; g++) { acc[i][g][0] = 0; acc[i][g][1] = 0; }
        gemm_acc<256, 2, 256, 128>(s_big, int_w2, acc, r0, c0);
        gemm_store<2, 128, false>(acc, int_b2, out_enriched + (size_t)b * 8192, r0, c0);
    }
}

extern "C" void kernel_launch(void* const* d_in, const int* in_sizes, int n_in,
                              void* d_out, int out_size)
{
    const float* obs       = (const float*)d_in[0];
    const float* enc_w1    = (const float*)d_in[1];
    const float* enc_b1    = (const float*)d_in[2];
    const float* enc_w2    = (const float*)d_in[3];
    const float* enc_b2    = (const float*)d_in[4];
    const float* in_proj_w = (const float*)d_in[5];
    const float* in_proj_b = (const float*)d_in[6];
    const float* out_w     = (const float*)d_in[7];
    const float* out_b     = (const float*)d_in[8];
    const float* int_w1    = (const float*)d_in[9];
    const float* int_b1    = (const float*)d_in[10];
    const float* ln_g      = (const float*)d_in[11];
    const float* ln_b      = (const float*)d_in[12];
    const float* int_w2    = (const float*)d_in[13];
    const float* int_b2    = (const float*)d_in[14];

    float* out_enriched = (float*)d_out;                            // (B,N,128)
    float* out_msgs     = (float*)d_out + (size_t)4096 * 64 * 128;  // (B,N,64)

    const int smem_bytes = 28672 * sizeof(float);  // 114688 = 112KB
    cudaFuncSetAttribute(comm_kernel, cudaFuncAttributeMaxDynamicSharedMemorySize, smem_bytes);

    comm_kernel<<<4096, 256, smem_bytes>>>(
        obs, enc_w1, enc_b1, enc_w2, enc_b2,
        in_proj_w, in_proj_b, out_w, out_b,
        int_w1, int_b1, ln_g, ln_b, int_w2, int_b2,
        out_enriched, out_msgs);
}